// round 12
// baseline (speedup 1.0000x reference)
#include <cuda_runtime.h>
#include <stdint.h>

// Canny magnitude, fully fused, float4, smem-aliased (22.6KB), arithmetic NMS dir,
// compiler-pipelined phase loops (no unroll-1 serialization).
// Input (16,3,512,512) f32, output (16,1,512,512) f32.

#define H_IMG 512
#define W_IMG 512
#define PLANE (H_IMG * W_IMG)
#define TX 64
#define TY 32
#define NT 256

#define GW 72   // gray stride (halo 4) = 18 float4
#define GH 40
#define HW 68   // h-blur stride (halo 2) = 17 float4
#define BH 36   // blur rows
#define BW 68   // blur stride (valid cols 0..67; P4 over-reads feed masked lanes)
#define MH 34
#define MW 68   // mag stride (valid cols 0..65; 66,67 pad = 0)

#define SA_F 2880               // gray 40*72; blur 36*68=2448 fits
#define MAG_F (MH * MW)         // 2312 floats
#define SB_F (MAG_F + 578)      // + 578 dir words

__device__ __forceinline__ int reflect_idx(int i, int n) {
    if (i < 0) i = -i;
    if (i >= n) i = 2 * n - 2 - i;
    return i;
}

// NMS linear offset in mag tile (stride 68), arithmetic (no LUT):
// dx = sign(gx) unless near-vertical; dy = -sign(gy) unless near-horizontal.
__device__ __forceinline__ int nms_dir(float gx, float gy) {
    float ax = fabsf(gx), ay = fabsf(gy);
    int sx = 1 | (__float_as_int(gx) >> 31);
    int sy = 1 | (__float_as_int(gy) >> 31);
    int dy = (ay > 0.4142135623730950f * ax) ? -sy : 0;
    int dx = (ay > 2.4142135623730950f * ax) ? 0 : sx;
    return dx + 68 * dy;
}

#define GQ0 0.054488684548643f
#define GQ1 0.244201342003233f
#define GQ2 0.402619946896247f

__global__ void __launch_bounds__(NT, 7)
canny_fused_kernel(const float* __restrict__ in, float* __restrict__ out) {
    __shared__ __align__(16) float sA[SA_F];   // gray -> blur
    __shared__ __align__(16) float sB[SB_F];   // htmp -> mag + dir words

    float*    sBlur = sA;
    float*    sMag  = sB;
    uint32_t* sDw   = (uint32_t*)(sB + MAG_F);
    int8_t*   sDb   = (int8_t*)(sB + MAG_F);

    const int tid = threadIdx.x;
    const int x0  = blockIdx.x * TX;
    const int y0  = blockIdx.y * TY;
    const int b   = blockIdx.z;

    const float* base = in + (size_t)b * 3 * PLANE;

    const bool interior = (x0 >= 4) && (x0 + TX + 4 <= W_IMG) &&
                          (y0 >= 4) && (y0 + TY + 4 <= H_IMG);

    // ---- Phase 1: grayscale into sA (GH x 18 f4 items = 720) ----
    if (interior) {
        const float* p = base + (y0 - 4) * W_IMG + (x0 - 4);  // 16B aligned
        #pragma unroll
        for (int it = 0; it < 3; it++) {
            int i = tid + it * NT;
            if (i < GH * 18) {
                int r = i / 18, c4 = (i - r * 18) * 4;
                const float* q = p + r * W_IMG + c4;
                float4 R = *(const float4*)q;
                float4 G = *(const float4*)(q + PLANE);
                float4 B = *(const float4*)(q + 2 * PLANE);
                float4 o;
                o.x = fmaf(0.1495f, R.x, fmaf(0.2935f, G.x, fmaf(0.057f, B.x, 0.5f)));
                o.y = fmaf(0.1495f, R.y, fmaf(0.2935f, G.y, fmaf(0.057f, B.y, 0.5f)));
                o.z = fmaf(0.1495f, R.z, fmaf(0.2935f, G.z, fmaf(0.057f, B.z, 0.5f)));
                o.w = fmaf(0.1495f, R.w, fmaf(0.2935f, G.w, fmaf(0.057f, B.w, 0.5f)));
                *(float4*)(sA + r * GW + c4) = o;
            }
        }
    } else {
        #pragma unroll 1
        for (int i = tid; i < GH * 18; i += NT) {
            int r = i / 18, c4 = (i - r * 18) * 4;
            int yy = reflect_idx(y0 - 4 + r, H_IMG) * W_IMG;
            float o[4];
            #pragma unroll
            for (int j = 0; j < 4; j++) {
                int off = yy + reflect_idx(x0 - 4 + c4 + j, W_IMG);
                o[j] = fmaf(0.1495f, base[off],
                       fmaf(0.2935f, base[off + PLANE],
                       fmaf(0.057f,  base[off + 2 * PLANE], 0.5f)));
            }
            *(float4*)(sA + r * GW + c4) = make_float4(o[0], o[1], o[2], o[3]);
        }
    }
    __syncthreads();

    // ---- Phase 2: horizontal blur sA(gray) -> sB(htmp), 680 items ----
    #pragma unroll
    for (int it = 0; it < 3; it++) {
        int i = tid + it * NT;
        if (i < GH * 17) {
            int r = i / 17, c4 = (i - r * 17) * 4;
            const float* g = sA + r * GW + c4;
            float4 a = *(const float4*)g;
            float4 c = *(const float4*)(g + 4);
            float4 o;
            o.x = GQ0 * (a.x + c.x) + GQ1 * (a.y + a.w) + GQ2 * a.z;
            o.y = GQ0 * (a.y + c.y) + GQ1 * (a.z + c.x) + GQ2 * a.w;
            o.z = GQ0 * (a.z + c.z) + GQ1 * (a.w + c.y) + GQ2 * c.x;
            o.w = GQ0 * (a.w + c.w) + GQ1 * (c.x + c.z) + GQ2 * c.y;
            *(float4*)(sB + r * HW + c4) = o;
        }
    }
    __syncthreads();

    // ---- Phase 3: vertical blur sB(htmp) -> sA(blur), 612 items ----
    #pragma unroll
    for (int it = 0; it < 3; it++) {
        int i = tid + it * NT;
        if (i < BH * 17) {
            int r = i / 17, c4 = (i - r * 17) * 4;
            const float* h = sB + r * HW + c4;
            float4 v0 = *(const float4*)h;
            float4 v1 = *(const float4*)(h + HW);
            float4 v2 = *(const float4*)(h + 2 * HW);
            float4 v3 = *(const float4*)(h + 3 * HW);
            float4 v4 = *(const float4*)(h + 4 * HW);
            float4 o;
            o.x = GQ0 * (v0.x + v4.x) + GQ1 * (v1.x + v3.x) + GQ2 * v2.x;
            o.y = GQ0 * (v0.y + v4.y) + GQ1 * (v1.y + v3.y) + GQ2 * v2.y;
            o.z = GQ0 * (v0.z + v4.z) + GQ1 * (v1.z + v3.z) + GQ2 * v2.z;
            o.w = GQ0 * (v0.w + v4.w) + GQ1 * (v1.w + v3.w) + GQ2 * v2.w;
            *(float4*)(sBlur + r * BW + c4) = o;
        }
    }
    __syncthreads();

    // ---- Phase 4: sobel + arithmetic dir -> sB(mag + packed dirs), 578 items ----
    if (interior) {
        #pragma unroll
        for (int it = 0; it < 3; it++) {
            int i = tid + it * NT;
            if (i < MH * 17) {
                int r = i / 17, c0 = (i - r * 17) * 4;
                const float* bp = sBlur + r * BW + c0;
                float t0[8], t1[8], t2[8];
                *(float4*)t0       = *(const float4*)bp;
                *(float4*)(t0 + 4) = *(const float4*)(bp + 4);
                *(float4*)t1       = *(const float4*)(bp + BW);
                *(float4*)(t1 + 4) = *(const float4*)(bp + BW + 4);
                *(float4*)t2       = *(const float4*)(bp + 2 * BW);
                *(float4*)(t2 + 4) = *(const float4*)(bp + 2 * BW + 4);
                float m[4];
                uint32_t dpack = 0;
                #pragma unroll
                for (int j = 0; j < 4; j++) {
                    float gx = (t0[j+2] - t0[j]) + 2.0f * (t1[j+2] - t1[j]) + (t2[j+2] - t2[j]);
                    float gy = (t2[j]   - t0[j]) + 2.0f * (t2[j+1] - t0[j+1]) + (t2[j+2] - t0[j+2]);
                    float mm = sqrtf(fmaf(gx, gx, fmaf(gy, gy, 1e-6f)));
                    int d = nms_dir(gx, gy);
                    if (c0 + j > 65) { mm = 0.0f; d = 1; }
                    m[j] = mm;
                    dpack |= ((uint32_t)(uint8_t)(int8_t)d) << (8 * j);
                }
                *(float4*)(sMag + r * MW + c0) = make_float4(m[0], m[1], m[2], m[3]);
                sDw[(r * MW + c0) >> 2] = dpack;
            }
        }
    } else {
        #pragma unroll 1
        for (int i = tid; i < MH * MW; i += NT) {
            int r = i / MW, c = i - r * MW;
            float mm = 0.0f;
            int8_t dch = 1;
            if (c <= 65) {
                int my = y0 - 1 + r;
                int mx = x0 - 1 + c;
                if (my >= 0 && my < H_IMG && mx >= 0 && mx < W_IMG) {
                    int iy0 = max(my - 1, 0)         - (y0 - 2);
                    int iy1 = r + 1;
                    int iy2 = min(my + 1, H_IMG - 1) - (y0 - 2);
                    int ix0 = max(mx - 1, 0)         - (x0 - 2);
                    int ix1 = c + 1;
                    int ix2 = min(mx + 1, W_IMG - 1) - (x0 - 2);
                    float b00 = sBlur[iy0*BW+ix0], b01 = sBlur[iy0*BW+ix1], b02 = sBlur[iy0*BW+ix2];
                    float b10 = sBlur[iy1*BW+ix0],                          b12 = sBlur[iy1*BW+ix2];
                    float b20 = sBlur[iy2*BW+ix0], b21 = sBlur[iy2*BW+ix1], b22 = sBlur[iy2*BW+ix2];
                    float gx = (b02 - b00) + 2.0f * (b12 - b10) + (b22 - b20);
                    float gy = (b20 - b00) + 2.0f * (b21 - b01) + (b22 - b02);
                    mm = sqrtf(fmaf(gx, gx, fmaf(gy, gy, 1e-6f)));
                    dch = (int8_t)nms_dir(gx, gy);
                }
            }
            sMag[i] = mm;
            sDb[i] = dch;
        }
    }
    __syncthreads();

    // ---- Phase 5: NMS, software-pipelined 2 items/thread ----
    float* obase = out + ((size_t)b * H_IMG + y0) * W_IMG + x0;

    const int i0  = tid;
    const int i1  = tid + NT;
    const int r0_ = i0 >> 4,          r1_ = i1 >> 4;
    const int ca  = (i0 & 15) * 4,    cb  = (i1 & 15) * 4;
    const int bs0 = (r0_ + 1) * MW + ca;
    const int bs1 = (r1_ + 1) * MW + cb;

    // issue all center loads + dir words up front (MLP)
    float4 A0 = *(const float4*)(sMag + bs0);
    float4 A1 = *(const float4*)(sMag + bs0 + 4);
    float4 B0 = *(const float4*)(sMag + bs1);
    float4 B1 = *(const float4*)(sMag + bs1 + 4);
    uint32_t wa0 = sDw[bs0 >> 2], wa1 = sDw[(bs0 >> 2) + 1];
    uint32_t wb0 = sDw[bs1 >> 2], wb1 = sDw[(bs1 >> 2) + 1];
    uint32_t dva = __funnelshift_r(wa0, wa1, 8);
    uint32_t dvb = __funnelshift_r(wb0, wb1, 8);

    {
        float ctr[4] = { A0.y, A0.z, A0.w, A1.x };
        float res[4];
        #pragma unroll
        for (int j = 0; j < 4; j++) {
            int d = (int)(int8_t)(dva >> (8 * j));
            int lin = bs0 + 1 + j;
            float mc = ctr[j];
            float sp = mc - sMag[lin + d];
            float sn = mc - sMag[lin - d];
            res[j] = (fminf(sp, sn) > 0.0f) ? mc : 0.0f;
        }
        *(float4*)(obase + r0_ * W_IMG + ca) = make_float4(res[0], res[1], res[2], res[3]);
    }
    {
        float ctr[4] = { B0.y, B0.z, B0.w, B1.x };
        float res[4];
        #pragma unroll
        for (int j = 0; j < 4; j++) {
            int d = (int)(int8_t)(dvb >> (8 * j));
            int lin = bs1 + 1 + j;
            float mc = ctr[j];
            float sp = mc - sMag[lin + d];
            float sn = mc - sMag[lin - d];
            res[j] = (fminf(sp, sn) > 0.0f) ? mc : 0.0f;
        }
        *(float4*)(obase + r1_ * W_IMG + cb) = make_float4(res[0], res[1], res[2], res[3]);
    }
}

extern "C" void kernel_launch(void* const* d_in, const int* in_sizes, int n_in,
                              void* d_out, int out_size) {
    const float* in = (const float*)d_in[0];
    float* out = (float*)d_out;
    dim3 grid(W_IMG / TX, H_IMG / TY, 16);   // (8, 16, 16)
    canny_fused_kernel<<<grid, NT>>>(in, out);
}